// round 4
// baseline (speedup 1.0000x reference)
#include <cuda_runtime.h>
#include <cuda_bf16.h>
#include <cstdint>

// S4D kernel materialization via bf16 mma.sync (HMMA) GEMM.
//   K[h, l] = Re( sum_n S0c[h,n] * w[h,n]^l ),  w = exp(dtA),  S0c = 2*C*(exp(dtA)-1)/A
// Chunk l = i + 64*j, i in [0,64), j in [0,128), z = w^64:
//   D[j,i] = sum_n Qr[n,j]*Pr[n,i] + (-Qi[n,j])*Pi[n,i],  Q = z^j,  P = S0c*w^i
// => per-h GEMM D = A @ B^T, A[128 x 64] = [Qr | -Qi] interleaved, B[64 x 64] = [Pr | Pi].
// bf16 with one error-split: D = Ah*Bh + Al*Bh + Ah*Bl (fp32 accum in registers).
// P/Q from fp64-phase-reduced tables; one complex mul per matrix element.

#define HH     1024
#define NHALF  32
#define LLEN   8192
#define TPB    128
#define PITCH  72                     // bf16 elems per row (64 + 8 pad): conflict-free frags

// byte offsets in dynamic smem
#define TAB_W0   0                    // [8][32]  float2  w^e
#define TAB_W1   2048                 // [8][32]  float2  S0c * w^(8e)
#define TAB_Z0   4096                 // [16][32] float2  w^(64e)
#define TAB_Z1   8192                 // [8][32]  float2  w^(1024e)
#define SM_AHI   12288                // 128 x PITCH bf16
#define SM_ALO   (SM_AHI + 128*PITCH*2)
#define SM_BHI   (SM_ALO + 128*PITCH*2)   // 64 x PITCH bf16
#define SM_BLO   (SM_BHI + 64*PITCH*2)
#define SM_TOTAL (SM_BLO + 64*PITCH*2)    // 67584 B

static __device__ __forceinline__ uint32_t pack_bf(float lo, float hi) {
    uint32_t r;
    asm("cvt.rn.bf16x2.f32 %0, %1, %2;" : "=r"(r) : "f"(hi), "f"(lo));
    return r;
}

static __device__ __forceinline__ void mma16816(float* c, const uint32_t* a,
                                                const uint32_t* b) {
    asm volatile(
        "mma.sync.aligned.m16n8k16.row.col.f32.bf16.bf16.f32 "
        "{%0,%1,%2,%3}, {%4,%5,%6,%7}, {%8,%9}, {%0,%1,%2,%3};"
        : "+f"(c[0]), "+f"(c[1]), "+f"(c[2]), "+f"(c[3])
        : "r"(a[0]), "r"(a[1]), "r"(a[2]), "r"(a[3]), "r"(b[0]), "r"(b[1]));
}

__global__ __launch_bounds__(TPB)
void s4d_kernel(const float* __restrict__ C,
                const float* __restrict__ log_dt,
                const float* __restrict__ log_A_real,
                const float* __restrict__ A_imag,
                float* __restrict__ out)
{
    extern __shared__ char smem[];
    const int h   = blockIdx.x;
    const int t   = threadIdx.x;
    const int wid = t >> 5;
    const int lid = t & 31;

    const double TWO_PI  = 6.283185307179586476925286766559;
    const double INV_2PI = 0.15915494309189533576888376337251;

    // ---- build tables: warp g computes one table for all 32 modes ----
    {
        const int n   = t & 31;
        const int grp = t >> 5;
        double dt = exp((double)log_dt[h]);
        double Ar = -exp((double)log_A_real[h * NHALF + n]);
        double Ai = (double)A_imag[h * NHALF + n];
        float darf = (float)(Ar * dt);
        float daif = (float)(Ai * dt);
        double dar = (double)darf, dai = (double)daif;

        double s0r = 1.0, s0i = 0.0;
        if (grp == 1) {  // fold S0c = 2*C*(exp(dtA)-1)/A into the W1 table
            double e1 = exp(dar);
            double cr = e1 * cos(dai) - 1.0, ci = e1 * sin(dai);
            double den = Ar * Ar + Ai * Ai;
            double qr = (cr * Ar + ci * Ai) / den;
            double qi = (ci * Ar - cr * Ai) / den;
            double Cr = (double)C[(h * NHALF + n) * 2 + 0];
            double Ci = (double)C[(h * NHALF + n) * 2 + 1];
            s0r = 2.0 * (Cr * qr - Ci * qi);
            s0i = 2.0 * (Cr * qi + Ci * qr);
        }

        int cnt, mul, taboff;
        if      (grp == 0) { cnt = 8;  mul = 1;    taboff = TAB_W0; }
        else if (grp == 1) { cnt = 8;  mul = 8;    taboff = TAB_W1; }
        else if (grp == 2) { cnt = 16; mul = 64;   taboff = TAB_Z0; }
        else               { cnt = 8;  mul = 1024; taboff = TAB_Z1; }

        float2* tab = (float2*)(smem + taboff);
        for (int e = 0; e < cnt; ++e) {
            double mm = (double)(e * mul);
            double th = dai * mm;                       // exact in double
            double kk = rint(th * INV_2PI);
            float thr = (float)fma(-kk, TWO_PI, th);    // |thr| <= pi
            float s, c;
            __sincosf(thr, &s, &c);
            float mg = __expf((float)(dar * mm));
            float br = mg * c, bi = mg * s;
            float vr = (float)(s0r * (double)br - s0i * (double)bi);
            float vi = (float)(s0r * (double)bi + s0i * (double)br);
            tab[e * 32 + n] = make_float2(vr, vi);
        }
    }
    __syncthreads();

    // ---- pack A = [Qr | -Qi] (128 x 64), hi/lo split ----
    {
        const int n = t & 31;
        const float2* Z0 = (const float2*)(smem + TAB_Z0);
        const float2* Z1 = (const float2*)(smem + TAB_Z1);
        const int jbase = (t >> 5) * 32;
#pragma unroll 4
        for (int jj = 0; jj < 32; ++jj) {
            int j = jbase + jj;
            float2 a = Z1[(j >> 4) * 32 + n];
            float2 b = Z0[(j & 15) * 32 + n];
            float v0 = a.x * b.x - a.y * b.y;           // Qr
            float v1 = -(a.x * b.y + a.y * b.x);        // -Qi
            uint32_t hp = pack_bf(v0, v1);
            float h0 = __uint_as_float(hp << 16);
            float h1 = __uint_as_float(hp & 0xFFFF0000u);
            uint32_t lp = pack_bf(v0 - h0, v1 - h1);
            uint32_t off = (uint32_t)(j * PITCH + 2 * n) * 2;
            *(uint32_t*)(smem + SM_AHI + off) = hp;
            *(uint32_t*)(smem + SM_ALO + off) = lp;
        }
    }
    // ---- pack B = [Pr | Pi] (64 x 64), hi/lo split ----
    {
        const int n = t & 31;
        const float2* W0 = (const float2*)(smem + TAB_W0);
        const float2* W1 = (const float2*)(smem + TAB_W1);
        const int ibase = (t >> 5) * 16;
#pragma unroll 4
        for (int ii = 0; ii < 16; ++ii) {
            int i = ibase + ii;
            float2 a = W1[(i >> 3) * 32 + n];
            float2 b = W0[(i & 7) * 32 + n];
            float v0 = a.x * b.x - a.y * b.y;           // Pr
            float v1 = a.x * b.y + a.y * b.x;           // Pi
            uint32_t hp = pack_bf(v0, v1);
            float h0 = __uint_as_float(hp << 16);
            float h1 = __uint_as_float(hp & 0xFFFF0000u);
            uint32_t lp = pack_bf(v0 - h0, v1 - h1);
            uint32_t off = (uint32_t)(i * PITCH + 2 * n) * 2;
            *(uint32_t*)(smem + SM_BHI + off) = hp;
            *(uint32_t*)(smem + SM_BLO + off) = lp;
        }
    }
    __syncthreads();

    // ---- GEMM: warp w owns rows w*32..w*32+31 (two m16 tiles) x 64 cols ----
    const int g   = lid >> 2;   // group (row within tile)
    const int tig = lid & 3;    // thread-in-group (col pair)

    float acc[2][8][4];
#pragma unroll
    for (int mt = 0; mt < 2; ++mt)
#pragma unroll
        for (int nt = 0; nt < 8; ++nt)
#pragma unroll
            for (int q = 0; q < 4; ++q) acc[mt][nt][q] = 0.0f;

#pragma unroll
    for (int p = 0; p < 3; ++p) {
        const char* Ab = smem + (p == 1 ? SM_ALO : SM_AHI);
        const char* Bb = smem + (p == 2 ? SM_BLO : SM_BHI);
#pragma unroll
        for (int kk = 0; kk < 4; ++kk) {
            const int c0 = kk * 16 + 2 * tig;
            uint32_t afr[2][4];
#pragma unroll
            for (int mt = 0; mt < 2; ++mt) {
                const int r = wid * 32 + mt * 16 + g;
                afr[mt][0] = *(const uint32_t*)(Ab + (size_t)(r * PITCH + c0) * 2);
                afr[mt][1] = *(const uint32_t*)(Ab + (size_t)((r + 8) * PITCH + c0) * 2);
                afr[mt][2] = *(const uint32_t*)(Ab + (size_t)(r * PITCH + c0 + 8) * 2);
                afr[mt][3] = *(const uint32_t*)(Ab + (size_t)((r + 8) * PITCH + c0 + 8) * 2);
            }
            uint32_t bfr[8][2];
#pragma unroll
            for (int nt = 0; nt < 8; ++nt) {
                const int nn = nt * 8 + g;
                bfr[nt][0] = *(const uint32_t*)(Bb + (size_t)(nn * PITCH + c0) * 2);
                bfr[nt][1] = *(const uint32_t*)(Bb + (size_t)(nn * PITCH + c0 + 8) * 2);
            }
#pragma unroll
            for (int mt = 0; mt < 2; ++mt)
#pragma unroll
                for (int nt = 0; nt < 8; ++nt)
                    mma16816(acc[mt][nt], afr[mt], bfr[nt]);
        }
    }

    // ---- epilogue: D[j,i] -> K[h, 64*j + i]  (float2 stores) ----
    float* basep = out + (size_t)h * LLEN;
#pragma unroll
    for (int mt = 0; mt < 2; ++mt) {
        const int r0 = wid * 32 + mt * 16 + g;
#pragma unroll
        for (int nt = 0; nt < 8; ++nt) {
            const int col = nt * 8 + 2 * tig;
            *(float2*)(basep + (size_t)r0 * 64 + col) =
                make_float2(acc[mt][nt][0], acc[mt][nt][1]);
            *(float2*)(basep + (size_t)(r0 + 8) * 64 + col) =
                make_float2(acc[mt][nt][2], acc[mt][nt][3]);
        }
    }
}

extern "C" void kernel_launch(void* const* d_in, const int* in_sizes, int n_in,
                              void* d_out, int out_size) {
    (void)in_sizes; (void)n_in; (void)out_size;
    const float* C          = (const float*)d_in[0];
    const float* log_dt     = (const float*)d_in[1];
    const float* log_A_real = (const float*)d_in[2];
    const float* A_imag     = (const float*)d_in[3];
    float* out = (float*)d_out;
    static int configured = 0;
    if (!configured) {
        cudaFuncSetAttribute(s4d_kernel, cudaFuncAttributeMaxDynamicSharedMemorySize,
                             SM_TOTAL);
        configured = 1;
    }
    s4d_kernel<<<HH, TPB, SM_TOTAL>>>(C, log_dt, log_A_real, A_imag, out);
}

// round 5
// speedup vs baseline: 4.5760x; 4.5760x over previous
#include <cuda_runtime.h>
#include <cuda_bf16.h>
#include <cstdint>

// S4D kernel materialization via bf16 mma.sync (HMMA), all-fp32 setup.
//   K[h, l] = Re( sum_n S0c[h,n] * w^l ),  w = exp(dtA),  S0c = 2*C*(exp(dtA)-1)/A
// l = i + 64*j:  D[j,i] = sum_n Qr[n,j]*Pr[n,i] + (-Qi[n,j])*Pi[n,i]
//   Q[j] = w^(64j) (from tables Z1[j>>4]*Z0[j&15]),  P[i] = S0c*w^i (W1[i>>3]*W0[i&7])
// GEMM D[128x64] = A[128x64] @ B[64x64]^T, A=[Qr|-Qi] computed on the fly in regs,
// B=[Pr|Pi] staged hi/lo in smem. 3 error-split passes: AhBh + AlBh + AhBl (fp32 acc).
// 256 threads/CTA, 8 warps, warp m-tile = 16. No fp64 anywhere (Cody-Waite fp32).

#define HH     1024
#define NHALF  32
#define LLEN   8192
#define TPB    256
#define PITCH  72        // bf16 per B row (64 + 8 pad) -> conflict-free fragment LDS

// dynamic smem byte offsets
#define TAB_W0   0                    // [8][32]  float2
#define TAB_W1   2048                 // [8][32]  float2 (S0c folded in)
#define TAB_Z0   4096                 // [16][32] float2
#define TAB_Z1   8192                 // [8][32]  float2
#define SM_BHI   10240                // 64 x PITCH bf16
#define SM_BLO   19456
#define SM_TOTAL 28672

static __device__ __forceinline__ uint32_t pack_bf(float lo, float hi) {
    uint32_t r;
    asm("cvt.rn.bf16x2.f32 %0, %1, %2;" : "=r"(r) : "f"(hi), "f"(lo));
    return r;
}
static __device__ __forceinline__ void mma16816(float* c, const uint32_t* a,
                                                uint32_t b0, uint32_t b1) {
    asm volatile(
        "mma.sync.aligned.m16n8k16.row.col.f32.bf16.bf16.f32 "
        "{%0,%1,%2,%3}, {%4,%5,%6,%7}, {%8,%9}, {%0,%1,%2,%3};"
        : "+f"(c[0]), "+f"(c[1]), "+f"(c[2]), "+f"(c[3])
        : "r"(a[0]), "r"(a[1]), "r"(a[2]), "r"(a[3]), "r"(b0), "r"(b1));
}

// fp32 Cody-Waite: reduce (daif*mm) mod 2pi. k*F1 exact (k<2^14, F1 has 9 bits).
#define F1_C     6.28125f
#define F2_C     ((float)(6.283185307179586476925286766559 - (double)6.28125f))
#define F3_C     ((float)(6.283185307179586476925286766559 - (double)6.28125f \
                          - (double)((float)(6.283185307179586476925286766559 - (double)6.28125f))))
#define INV2PI_C 0.15915494309189533f

static __device__ __forceinline__ float reduce_phase(float daif, float mmf) {
    float hi = daif * mmf;
    float lo = fmaf(daif, mmf, -hi);           // exact residual (mm < 2^13 int)
    float k  = rintf(hi * INV2PI_C);
    float r  = fmaf(-k, F1_C, hi);
    r = fmaf(-k, F2_C, r);
    r = fmaf(-k, F3_C, r);
    return r + lo;
}

__global__ __launch_bounds__(TPB, 3)
void s4d_kernel(const float* __restrict__ C,
                const float* __restrict__ log_dt,
                const float* __restrict__ log_A_real,
                const float* __restrict__ A_imag,
                float* __restrict__ out)
{
    extern __shared__ char smem[];
    const int h   = blockIdx.x;
    const int t   = threadIdx.x;
    const int wid = t >> 5;
    const int lid = t & 31;

    // ---- per-mode params (fp32, matches reference's fp32 arithmetic) ----
    const int n = lid;
    const float ldt  = log_dt[h];
    const float lar  = log_A_real[h * NHALF + n];
    const float Ai   = A_imag[h * NHALF + n];
    const float dt   = __expf(ldt);
    const float Arf  = -__expf(lar);
    const float darf = Arf * dt;
    const float daif = Ai * dt;

    // ---- table build: warps 0-4, 8 elements each ----
    if (wid < 5) {
        float s0r = 1.0f, s0i = 0.0f;
        if (wid == 1) {  // fold S0c = 2*C*(exp(dtA)-1)/A into W1
            float rd = reduce_phase(daif, 1.0f);
            float sd, cd;
            __sincosf(rd, &sd, &cd);
            float e1 = __expf(darf);
            float cr = e1 * cd - 1.0f;
            float ci = e1 * sd;
            float inv = __frcp_rn(Arf * Arf + Ai * Ai);
            float qr = (cr * Arf + ci * Ai) * inv;
            float qi = (ci * Arf - cr * Ai) * inv;
            float Cr = C[(h * NHALF + n) * 2 + 0];
            float Ci = C[(h * NHALF + n) * 2 + 1];
            s0r = 2.0f * (Cr * qr - Ci * qi);
            s0i = 2.0f * (Cr * qi + Ci * qr);
        }
        int mul, ebase, taboff;
        if      (wid == 0) { mul = 1;    ebase = 0; taboff = TAB_W0; }
        else if (wid == 1) { mul = 8;    ebase = 0; taboff = TAB_W1; }
        else if (wid == 2) { mul = 64;   ebase = 0; taboff = TAB_Z0; }
        else if (wid == 3) { mul = 64;   ebase = 8; taboff = TAB_Z0; }
        else               { mul = 1024; ebase = 0; taboff = TAB_Z1; }

        float2* tab = (float2*)(smem + taboff);
#pragma unroll
        for (int e2 = 0; e2 < 8; ++e2) {
            int   e   = ebase + e2;
            float mmf = (float)(e * mul);
            float r   = reduce_phase(daif, mmf);
            float s, c;
            __sincosf(r, &s, &c);
            float mg = __expf(darf * mmf);
            float br = mg * c, bi = mg * s;
            tab[e * 32 + n] = make_float2(s0r * br - s0i * bi,
                                          s0r * bi + s0i * br);
        }
    }
    __syncthreads();

    // ---- stage B = [Pr | Pi] (64 x 64) hi/lo: warp w -> rows w*8..w*8+7 ----
    {
        const float2* W0 = (const float2*)(smem + TAB_W0);
        const float2* W1 = (const float2*)(smem + TAB_W1);
        float2 w1 = W1[wid * 32 + n];
#pragma unroll
        for (int r = 0; r < 8; ++r) {
            int i = wid * 8 + r;
            float2 w0 = W0[r * 32 + n];
            float pr = w1.x * w0.x - w1.y * w0.y;
            float pi = w1.x * w0.y + w1.y * w0.x;
            uint32_t hp = pack_bf(pr, pi);
            float h0 = __uint_as_float(hp << 16);
            float h1 = __uint_as_float(hp & 0xFFFF0000u);
            uint32_t lp = pack_bf(pr - h0, pi - h1);
            uint32_t off = (uint32_t)(i * PITCH * 2 + 4 * n);
            *(uint32_t*)(smem + SM_BHI + off) = hp;
            *(uint32_t*)(smem + SM_BLO + off) = lp;
        }
    }
    __syncthreads();

    // ---- GEMM: warp wid -> rows wid*16 .. +15 (one m16 tile) x 64 cols ----
    const int g   = lid >> 2;
    const int tig = lid & 3;

    float acc[8][4];
#pragma unroll
    for (int nt = 0; nt < 8; ++nt)
#pragma unroll
        for (int q = 0; q < 4; ++q) acc[nt][q] = 0.0f;

    const float2* Z0p = (const float2*)(smem + TAB_Z0);
    const float2* Z1p = (const float2*)(smem + TAB_Z1);

#pragma unroll
    for (int kk = 0; kk < 4; ++kk) {
        const int n0 = kk * 8 + tig, n1 = n0 + 4;

        // A fragments on the fly: rows j0 = wid*16+g (j0>>4 = wid, j0&15 = g),
        //                         j1 = j0+8   (j1>>4 = wid, j1&15 = g+8)
        float2 zh0 = Z1p[wid * 32 + n0];
        float2 zh1 = Z1p[wid * 32 + n1];
        float2 za  = Z0p[g * 32 + n0];
        float2 zb  = Z0p[g * 32 + n1];
        float2 zc  = Z0p[(g + 8) * 32 + n0];
        float2 zd  = Z0p[(g + 8) * 32 + n1];

        float q0r = zh0.x * za.x - zh0.y * za.y, q0i = zh0.x * za.y + zh0.y * za.x;
        float q1r = zh0.x * zc.x - zh0.y * zc.y, q1i = zh0.x * zc.y + zh0.y * zc.x;
        float q2r = zh1.x * zb.x - zh1.y * zb.y, q2i = zh1.x * zb.y + zh1.y * zb.x;
        float q3r = zh1.x * zd.x - zh1.y * zd.y, q3i = zh1.x * zd.y + zh1.y * zd.x;

        uint32_t Ah[4], Al[4];
        {
            float vr[4] = {q0r, q1r, q2r, q3r};
            float vi[4] = {-q0i, -q1i, -q2i, -q3i};
#pragma unroll
            for (int q = 0; q < 4; ++q) {
                uint32_t hp = pack_bf(vr[q], vi[q]);
                float h0 = __uint_as_float(hp << 16);
                float h1 = __uint_as_float(hp & 0xFFFF0000u);
                Ah[q] = hp;
                Al[q] = pack_bf(vr[q] - h0, vi[q] - h1);
            }
        }

        const char* bh = smem + SM_BHI + kk * 32 + 4 * tig;
        const char* bl = smem + SM_BLO + kk * 32 + 4 * tig;
#pragma unroll
        for (int nt = 0; nt < 8; ++nt) {
            const int ro = (nt * 8 + g) * (PITCH * 2);
            uint32_t b0 = *(const uint32_t*)(bh + ro);
            uint32_t b1 = *(const uint32_t*)(bh + ro + 16);
            uint32_t l0 = *(const uint32_t*)(bl + ro);
            uint32_t l1 = *(const uint32_t*)(bl + ro + 16);
            mma16816(acc[nt], Ah, b0, b1);   // Ah*Bh
            mma16816(acc[nt], Al, b0, b1);   // Al*Bh
            mma16816(acc[nt], Ah, l0, l1);   // Ah*Bl
        }
    }

    // ---- epilogue: D[j,i] -> K[h, 64*j + i] ----
    float* bp = out + (size_t)h * LLEN;
    const int j0 = wid * 16 + g;
#pragma unroll
    for (int nt = 0; nt < 8; ++nt) {
        const int col = nt * 8 + 2 * tig;
        *(float2*)(bp + (size_t)j0 * 64 + col)       = make_float2(acc[nt][0], acc[nt][1]);
        *(float2*)(bp + (size_t)(j0 + 8) * 64 + col) = make_float2(acc[nt][2], acc[nt][3]);
    }
}

extern "C" void kernel_launch(void* const* d_in, const int* in_sizes, int n_in,
                              void* d_out, int out_size) {
    (void)in_sizes; (void)n_in; (void)out_size;
    const float* C          = (const float*)d_in[0];
    const float* log_dt     = (const float*)d_in[1];
    const float* log_A_real = (const float*)d_in[2];
    const float* A_imag     = (const float*)d_in[3];
    float* out = (float*)d_out;
    s4d_kernel<<<HH, TPB, SM_TOTAL>>>(C, log_dt, log_A_real, A_imag, out);
}

// round 6
// speedup vs baseline: 5.0267x; 1.0985x over previous
#include <cuda_runtime.h>
#include <cuda_bf16.h>
#include <cstdint>

// S4D kernel materialization via bf16 mma.sync (HMMA), all-fp32 setup.
//   K[h, l] = Re( sum_n S0c[h,n] * w^l ),  w = exp(dtA),  S0c = 2*C*(exp(dtA)-1)/A
// l = i + 64*j:  D[j,i] = sum_n Qr[n,j]*Pr[n,i] + (-Qi[n,j])*Pi[n,i]
// GEMM D[128x64] = A[128x64] @ B[64x64]^T, A=[Qr|-Qi] on the fly (regs),
// B=[Pr|Pi] staged hi/lo in smem. 3 error-split passes (fp32 acc).
// 4 warps/CTA, M=32 per warp: B re-read 4x/CTA instead of 8x (halves L1 LDS).
// A-fragments for all kk precomputed once into registers; nt-outer loop.

#define HH     1024
#define NHALF  32
#define LLEN   8192
#define TPB    128
#define PITCH  72        // bf16 per B row (64 + 8 pad): conflict-free fragment LDS

// dynamic smem byte offsets
#define TAB_W0   0                    // [8][32]  float2
#define TAB_W1   2048                 // [8][32]  float2 (S0c folded in)
#define TAB_Z0   4096                 // [16][32] float2
#define TAB_Z1   8192                 // [8][32]  float2
#define SM_BHI   10240                // 64 x PITCH bf16
#define SM_BLO   19456
#define SM_TOTAL 28672

static __device__ __forceinline__ uint32_t pack_bf(float lo, float hi) {
    uint32_t r;
    asm("cvt.rn.bf16x2.f32 %0, %1, %2;" : "=r"(r) : "f"(hi), "f"(lo));
    return r;
}
static __device__ __forceinline__ void mma16816(float* c, const uint32_t* a,
                                                uint32_t b0, uint32_t b1) {
    asm volatile(
        "mma.sync.aligned.m16n8k16.row.col.f32.bf16.bf16.f32 "
        "{%0,%1,%2,%3}, {%4,%5,%6,%7}, {%8,%9}, {%0,%1,%2,%3};"
        : "+f"(c[0]), "+f"(c[1]), "+f"(c[2]), "+f"(c[3])
        : "r"(a[0]), "r"(a[1]), "r"(a[2]), "r"(a[3]), "r"(b0), "r"(b1));
}

// fp32 Cody-Waite: reduce (daif*mm) mod 2pi. k*F1 exact (k<2^14, F1 has 9 bits).
#define F1_C     6.28125f
#define F2_C     ((float)(6.283185307179586476925286766559 - (double)6.28125f))
#define F3_C     ((float)(6.283185307179586476925286766559 - (double)6.28125f \
                          - (double)((float)(6.283185307179586476925286766559 - (double)6.28125f))))
#define INV2PI_C 0.15915494309189533f

static __device__ __forceinline__ float reduce_phase(float daif, float mmf) {
    float hi = daif * mmf;
    float lo = fmaf(daif, mmf, -hi);           // exact residual
    float k  = rintf(hi * INV2PI_C);
    float r  = fmaf(-k, F1_C, hi);
    r = fmaf(-k, F2_C, r);
    r = fmaf(-k, F3_C, r);
    return r + lo;
}

__global__ __launch_bounds__(TPB, 4)
void s4d_kernel(const float* __restrict__ C,
                const float* __restrict__ log_dt,
                const float* __restrict__ log_A_real,
                const float* __restrict__ A_imag,
                float* __restrict__ out)
{
    extern __shared__ char smem[];
    const int h   = blockIdx.x;
    const int t   = threadIdx.x;
    const int wid = t >> 5;
    const int lid = t & 31;
    const int n   = lid;

    // ---- per-mode params (fp32, matches reference rounding) ----
    const float dt   = __expf(log_dt[h]);
    const float Arf  = -__expf(log_A_real[h * NHALF + n]);
    const float Ai   = A_imag[h * NHALF + n];
    const float darf = Arf * dt;
    const float daif = Ai * dt;

    // ---- table build: 4 warps cover 5 groups (warp0 does two) ----
    {
        float s0r = 1.0f, s0i = 0.0f;
        if (wid == 1) {  // fold S0c = 2*C*(exp(dtA)-1)/A into W1
            float rd = reduce_phase(daif, 1.0f);
            float sd, cd;
            __sincosf(rd, &sd, &cd);
            float e1 = __expf(darf);
            float cr = e1 * cd - 1.0f;
            float ci = e1 * sd;
            float inv = __frcp_rn(Arf * Arf + Ai * Ai);
            float qr = (cr * Arf + ci * Ai) * inv;
            float qi = (ci * Arf - cr * Ai) * inv;
            float Cr = C[(h * NHALF + n) * 2 + 0];
            float Ci = C[(h * NHALF + n) * 2 + 1];
            s0r = 2.0f * (Cr * qr - Ci * qi);
            s0i = 2.0f * (Cr * qi + Ci * qr);
        }
        int nt_tasks = (wid == 0) ? 2 : 1;
        for (int task = 0; task < nt_tasks; ++task) {
            int mul, ebase, taboff;
            if (wid == 0) {
                if (task == 0) { mul = 1;    ebase = 0; taboff = TAB_W0; }
                else           { mul = 1024; ebase = 0; taboff = TAB_Z1; }
            }
            else if (wid == 1) { mul = 8;  ebase = 0; taboff = TAB_W1; }
            else if (wid == 2) { mul = 64; ebase = 0; taboff = TAB_Z0; }
            else               { mul = 64; ebase = 8; taboff = TAB_Z0; }

            float2* tab = (float2*)(smem + taboff);
#pragma unroll
            for (int e2 = 0; e2 < 8; ++e2) {
                int   e   = ebase + e2;
                float mmf = (float)(e * mul);
                float r   = reduce_phase(daif, mmf);
                float s, c;
                __sincosf(r, &s, &c);
                float mg = __expf(darf * mmf);
                float br = mg * c, bi = mg * s;
                tab[e * 32 + n] = make_float2(s0r * br - s0i * bi,
                                              s0r * bi + s0i * br);
            }
        }
    }
    __syncthreads();

    // ---- stage B = [Pr | Pi] (64 x 64) hi/lo: warp w -> rows w*16..+15 ----
    {
        const float2* W0 = (const float2*)(smem + TAB_W0);
        const float2* W1 = (const float2*)(smem + TAB_W1);
#pragma unroll
        for (int r = 0; r < 16; ++r) {
            int i = wid * 16 + r;
            float2 w1 = W1[(i >> 3) * 32 + n];
            float2 w0 = W0[(i & 7) * 32 + n];
            float pr = w1.x * w0.x - w1.y * w0.y;
            float pi = w1.x * w0.y + w1.y * w0.x;
            uint32_t hp = pack_bf(pr, pi);
            float h0 = __uint_as_float(hp << 16);
            float h1 = __uint_as_float(hp & 0xFFFF0000u);
            uint32_t lp = pack_bf(pr - h0, pi - h1);
            uint32_t off = (uint32_t)(i * PITCH * 2 + 4 * n);
            *(uint32_t*)(smem + SM_BHI + off) = hp;
            *(uint32_t*)(smem + SM_BLO + off) = lp;
        }
    }
    __syncthreads();

    // ---- precompute A fragments for all kk, both m-tiles ----
    const int g   = lid >> 2;
    const int tig = lid & 3;
    const float2* Z0p = (const float2*)(smem + TAB_Z0);
    const float2* Z1p = (const float2*)(smem + TAB_Z1);

    uint32_t Ah[4][2][4], Al[4][2][4];
#pragma unroll
    for (int kk = 0; kk < 4; ++kk) {
        const int n0 = kk * 8 + tig, n1 = n0 + 4;
        float2 za = Z0p[g * 32 + n0];
        float2 zb = Z0p[g * 32 + n1];
        float2 zc = Z0p[(g + 8) * 32 + n0];
        float2 zd = Z0p[(g + 8) * 32 + n1];
#pragma unroll
        for (int mt = 0; mt < 2; ++mt) {
            float2 zh0 = Z1p[(wid * 2 + mt) * 32 + n0];
            float2 zh1 = Z1p[(wid * 2 + mt) * 32 + n1];
            // rows j = wid*32 + mt*16 + {g, g+8}; cols n0 (a0,a1), n1 (a2,a3)
            float vr[4], vi[4];
            vr[0] = zh0.x * za.x - zh0.y * za.y;  vi[0] = -(zh0.x * za.y + zh0.y * za.x);
            vr[1] = zh0.x * zc.x - zh0.y * zc.y;  vi[1] = -(zh0.x * zc.y + zh0.y * zc.x);
            vr[2] = zh1.x * zb.x - zh1.y * zb.y;  vi[2] = -(zh1.x * zb.y + zh1.y * zb.x);
            vr[3] = zh1.x * zd.x - zh1.y * zd.y;  vi[3] = -(zh1.x * zd.y + zh1.y * zd.x);
#pragma unroll
            for (int q = 0; q < 4; ++q) {
                uint32_t hp = pack_bf(vr[q], vi[q]);
                float h0 = __uint_as_float(hp << 16);
                float h1 = __uint_as_float(hp & 0xFFFF0000u);
                Ah[kk][mt][q] = hp;
                Al[kk][mt][q] = pack_bf(vr[q] - h0, vi[q] - h1);
            }
        }
    }

    // ---- GEMM, nt-outer: B frags loaded once, used by both m-tiles ----
    float* bp = out + (size_t)h * LLEN;
    const int j0 = wid * 32 + g;

#pragma unroll
    for (int nt = 0; nt < 8; ++nt) {
        float acc0[4] = {0.f, 0.f, 0.f, 0.f};
        float acc1[4] = {0.f, 0.f, 0.f, 0.f};
        const char* bh = smem + SM_BHI + (nt * 8 + g) * (PITCH * 2) + 4 * tig;
        const char* bl = smem + SM_BLO + (nt * 8 + g) * (PITCH * 2) + 4 * tig;
#pragma unroll
        for (int kk = 0; kk < 4; ++kk) {
            uint32_t b0 = *(const uint32_t*)(bh + kk * 32);
            uint32_t b1 = *(const uint32_t*)(bh + kk * 32 + 16);
            uint32_t l0 = *(const uint32_t*)(bl + kk * 32);
            uint32_t l1 = *(const uint32_t*)(bl + kk * 32 + 16);
            mma16816(acc0, Ah[kk][0], b0, b1);
            mma16816(acc1, Ah[kk][1], b0, b1);
            mma16816(acc0, Al[kk][0], b0, b1);
            mma16816(acc1, Al[kk][1], b0, b1);
            mma16816(acc0, Ah[kk][0], l0, l1);
            mma16816(acc1, Ah[kk][1], l0, l1);
        }
        const int col = nt * 8 + 2 * tig;
        *(float2*)(bp + (size_t)j0 * 64 + col)        = make_float2(acc0[0], acc0[1]);
        *(float2*)(bp + (size_t)(j0 + 8) * 64 + col)  = make_float2(acc0[2], acc0[3]);
        *(float2*)(bp + (size_t)(j0 + 16) * 64 + col) = make_float2(acc1[0], acc1[1]);
        *(float2*)(bp + (size_t)(j0 + 24) * 64 + col) = make_float2(acc1[2], acc1[3]);
    }
}

extern "C" void kernel_launch(void* const* d_in, const int* in_sizes, int n_in,
                              void* d_out, int out_size) {
    (void)in_sizes; (void)n_in; (void)out_size;
    const float* C          = (const float*)d_in[0];
    const float* log_dt     = (const float*)d_in[1];
    const float* log_A_real = (const float*)d_in[2];
    const float* A_imag     = (const float*)d_in[3];
    float* out = (float*)d_out;
    s4d_kernel<<<HH, TPB, SM_TOTAL>>>(C, log_dt, log_A_real, A_imag, out);
}

// round 8
// speedup vs baseline: 5.5554x; 1.1052x over previous
#include <cuda_runtime.h>
#include <cuda_bf16.h>
#include <cstdint>

// S4D kernel materialization via bf16 mma.sync (HMMA), all-fp32 setup.
//   K[h, l] = Re( sum_n S0c[h,n] * w^l ),  w = exp(dtA),  S0c = 2*C*(exp(dtA)-1)/A
// l = i + 64*j:  D[j,i] = sum_n Qr[n,j]*Pr[n,i] + (-Qi[n,j])*Pi[n,i]
// GEMM D[128x64] = A[128x64] @ B[64x64]^T, A=[Qr|-Qi] on the fly (regs),
// B=[Pr|Pi] staged hi+lo interleaved 16B entries -> one LDS.128 per (nt,kk).
// 3 error-split passes: AhBh + AlBh + AhBl (fp32 acc). Tables built
// incrementally (1 sincos/exp + 7 complex muls) instead of 8 sincos.

#define HH     1024
#define NHALF  32
#define LLEN   8192
#define TPB    128

// dynamic smem byte offsets
#define TAB_W0   0                    // [8][32]  float2
#define TAB_W1   2048                 // [8][32]  float2 (S0c folded in)
#define TAB_Z0   4096                 // [16][32] float2
#define TAB_Z1   8192                 // [8][32]  float2
#define SM_B     10240                // 64 rows x 320B  (16B entry [i][kk][tig])
#define BROWS    320                  // stride/16 = 20 ≡ 4 (mod 8) -> conflict-free LDS.128
#define SM_TOTAL (SM_B + 64 * BROWS)  // 30720

static __device__ __forceinline__ uint32_t pack_bf(float lo, float hi) {
    uint32_t r;
    asm("cvt.rn.bf16x2.f32 %0, %1, %2;" : "=r"(r) : "f"(hi), "f"(lo));
    return r;
}
static __device__ __forceinline__ void mma16816(float* c, const uint32_t* a,
                                                uint32_t b0, uint32_t b1) {
    asm volatile(
        "mma.sync.aligned.m16n8k16.row.col.f32.bf16.bf16.f32 "
        "{%0,%1,%2,%3}, {%4,%5,%6,%7}, {%8,%9}, {%0,%1,%2,%3};"
        : "+f"(c[0]), "+f"(c[1]), "+f"(c[2]), "+f"(c[3])
        : "r"(a[0]), "r"(a[1]), "r"(a[2]), "r"(a[3]), "r"(b0), "r"(b1));
}

// fp32 Cody-Waite: reduce (daif*mm) mod 2pi. k*F1 exact (k<2^14, F1 has 9 bits).
#define F1_C     6.28125f
#define F2_C     ((float)(6.283185307179586476925286766559 - (double)6.28125f))
#define F3_C     ((float)(6.283185307179586476925286766559 - (double)6.28125f \
                          - (double)((float)(6.283185307179586476925286766559 - (double)6.28125f))))
#define INV2PI_C 0.15915494309189533f

static __device__ __forceinline__ float reduce_phase(float daif, float mmf) {
    float hi = daif * mmf;
    float lo = fmaf(daif, mmf, -hi);           // exact residual
    float k  = rintf(hi * INV2PI_C);
    float r  = fmaf(-k, F1_C, hi);
    r = fmaf(-k, F2_C, r);
    r = fmaf(-k, F3_C, r);
    return r + lo;
}

// exp(dtA * mm) in fp32 with reduced phase
static __device__ __forceinline__ float2 cexp_dta(float darf, float daif, float mmf) {
    float r = reduce_phase(daif, mmf);
    float s, c;
    __sincosf(r, &s, &c);
    float mg = __expf(darf * mmf);
    return make_float2(mg * c, mg * s);
}

__global__ __launch_bounds__(TPB, 4)
void s4d_kernel(const float* __restrict__ C,
                const float* __restrict__ log_dt,
                const float* __restrict__ log_A_real,
                const float* __restrict__ A_imag,
                float* __restrict__ out)
{
    extern __shared__ char smem[];
    const int h   = blockIdx.x;
    const int t   = threadIdx.x;
    const int wid = t >> 5;
    const int lid = t & 31;
    const int n   = lid;

    // ---- per-mode params (fp32, matches reference rounding) ----
    const float dt   = __expf(log_dt[h]);
    const float Arf  = -__expf(log_A_real[h * NHALF + n]);
    const float Ai   = A_imag[h * NHALF + n];
    const float darf = Arf * dt;
    const float daif = Ai * dt;

    // ---- incremental table build: 1 direct eval + 7 dependent cmuls ----
    {
        float2 seed = make_float2(1.0f, 0.0f);
        if (wid == 1) {  // fold S0c = 2*C*(exp(dtA)-1)/A into W1
            float2 e1 = cexp_dta(darf, daif, 1.0f);
            float cr = e1.x - 1.0f, ci = e1.y;
            float inv = __frcp_rn(Arf * Arf + Ai * Ai);
            float qr = (cr * Arf + ci * Ai) * inv;
            float qi = (ci * Arf - cr * Ai) * inv;
            float Cr = C[(h * NHALF + n) * 2 + 0];
            float Ci = C[(h * NHALF + n) * 2 + 1];
            seed = make_float2(2.0f * (Cr * qr - Ci * qi),
                               2.0f * (Cr * qi + Ci * qr));
        }
        int nt_tasks = (wid == 0) ? 2 : 1;
        for (int task = 0; task < nt_tasks; ++task) {
            int mul, ebase, taboff;
            if (wid == 0) {
                if (task == 0) { mul = 1;    ebase = 0; taboff = TAB_W0; }
                else           { mul = 1024; ebase = 0; taboff = TAB_Z1; }
            }
            else if (wid == 1) { mul = 8;  ebase = 0; taboff = TAB_W1; }
            else if (wid == 2) { mul = 64; ebase = 0; taboff = TAB_Z0; }
            else               { mul = 64; ebase = 8; taboff = TAB_Z0; }

            float2 base = cexp_dta(darf, daif, (float)mul);
            float2 cur;
            if (ebase == 0) cur = seed;     // e=0: w^0 (or S0c for W1)
            else {                           // warp 3: direct eval at e=8
                float2 c8 = cexp_dta(darf, daif, (float)(8 * mul));
                cur = c8;
            }
            float2* tab = (float2*)(smem + taboff);
            tab[ebase * 32 + n] = cur;
#pragma unroll
            for (int e2 = 1; e2 < 8; ++e2) {
                float nr = cur.x * base.x - cur.y * base.y;
                float ni = cur.x * base.y + cur.y * base.x;
                cur = make_float2(nr, ni);
                tab[(ebase + e2) * 32 + n] = cur;
            }
        }
    }
    __syncthreads();

    // ---- stage B: entry16[i][kk][tig] = {bhi(n0), blo(n0), bhi(n1), blo(n1)} ----
    // this thread (mode n, rows i) contributes the 8-byte half for its n:
    //   kk = n>>3, tig = n&3, half = (n>>2)&1
    {
        const float2* W0 = (const float2*)(smem + TAB_W0);
        const float2* W1 = (const float2*)(smem + TAB_W1);
        const uint32_t eoff = (uint32_t)((n >> 3) * 64 + (n & 3) * 16 + ((n >> 2) & 1) * 8);
#pragma unroll
        for (int r = 0; r < 16; ++r) {
            int i = wid * 16 + r;
            float2 w1 = W1[(i >> 3) * 32 + n];
            float2 w0 = W0[(i & 7) * 32 + n];
            float pr = w1.x * w0.x - w1.y * w0.y;
            float pi = w1.x * w0.y + w1.y * w0.x;
            uint32_t hp = pack_bf(pr, pi);
            float h0 = __uint_as_float(hp << 16);
            float h1 = __uint_as_float(hp & 0xFFFF0000u);
            uint32_t lp = pack_bf(pr - h0, pi - h1);
            *(uint2*)(smem + SM_B + (uint32_t)i * BROWS + eoff) = make_uint2(hp, lp);
        }
    }
    __syncthreads();

    // ---- precompute A fragments for all kk, both m-tiles ----
    const int g   = lid >> 2;
    const int tig = lid & 3;
    const float2* Z0p = (const float2*)(smem + TAB_Z0);
    const float2* Z1p = (const float2*)(smem + TAB_Z1);

    uint32_t Ah[4][2][4], Al[4][2][4];
#pragma unroll
    for (int kk = 0; kk < 4; ++kk) {
        const int n0 = kk * 8 + tig, n1 = n0 + 4;
        float2 za = Z0p[g * 32 + n0];
        float2 zb = Z0p[g * 32 + n1];
        float2 zc = Z0p[(g + 8) * 32 + n0];
        float2 zd = Z0p[(g + 8) * 32 + n1];
#pragma unroll
        for (int mt = 0; mt < 2; ++mt) {
            float2 zh0 = Z1p[(wid * 2 + mt) * 32 + n0];
            float2 zh1 = Z1p[(wid * 2 + mt) * 32 + n1];
            float vr[4], vi[4];
            vr[0] = zh0.x * za.x - zh0.y * za.y;  vi[0] = -(zh0.x * za.y + zh0.y * za.x);
            vr[1] = zh0.x * zc.x - zh0.y * zc.y;  vi[1] = -(zh0.x * zc.y + zh0.y * zc.x);
            vr[2] = zh1.x * zb.x - zh1.y * zb.y;  vi[2] = -(zh1.x * zb.y + zh1.y * zb.x);
            vr[3] = zh1.x * zd.x - zh1.y * zd.y;  vi[3] = -(zh1.x * zd.y + zh1.y * zd.x);
#pragma unroll
            for (int q = 0; q < 4; ++q) {
                uint32_t hp = pack_bf(vr[q], vi[q]);
                float h0 = __uint_as_float(hp << 16);
                float h1 = __uint_as_float(hp & 0xFFFF0000u);
                Ah[kk][mt][q] = hp;
                Al[kk][mt][q] = pack_bf(vr[q] - h0, vi[q] - h1);
            }
        }
    }

    // ---- GEMM, nt-outer: one LDS.128 per (nt,kk) fetches b0,l0,b1,l1 ----
    float* bp = out + (size_t)h * LLEN;
    const int j0 = wid * 32 + g;

#pragma unroll
    for (int nt = 0; nt < 8; ++nt) {
        float acc0[4] = {0.f, 0.f, 0.f, 0.f};
        float acc1[4] = {0.f, 0.f, 0.f, 0.f};
        const char* brow = smem + SM_B + (uint32_t)(nt * 8 + g) * BROWS + tig * 16;
#pragma unroll
        for (int kk = 0; kk < 4; ++kk) {
            uint4 bv = *(const uint4*)(brow + kk * 64);   // {b0, l0, b1, l1}
            mma16816(acc0, Ah[kk][0], bv.x, bv.z);
            mma16816(acc1, Ah[kk][1], bv.x, bv.z);
            mma16816(acc0, Al[kk][0], bv.x, bv.z);
            mma16816(acc1, Al[kk][1], bv.x, bv.z);
            mma16816(acc0, Ah[kk][0], bv.y, bv.w);
            mma16816(acc1, Ah[kk][1], bv.y, bv.w);
        }
        const int col = nt * 8 + 2 * tig;
        *(float2*)(bp + (size_t)j0 * 64 + col)        = make_float2(acc0[0], acc0[1]);
        *(float2*)(bp + (size_t)(j0 + 8) * 64 + col)  = make_float2(acc0[2], acc0[3]);
        *(float2*)(bp + (size_t)(j0 + 16) * 64 + col) = make_float2(acc1[0], acc1[1]);
        *(float2*)(bp + (size_t)(j0 + 24) * 64 + col) = make_float2(acc1[2], acc1[3]);
    }
}

extern "C" void kernel_launch(void* const* d_in, const int* in_sizes, int n_in,
                              void* d_out, int out_size) {
    (void)in_sizes; (void)n_in; (void)out_size;
    const float* C          = (const float*)d_in[0];
    const float* log_dt     = (const float*)d_in[1];
    const float* log_A_real = (const float*)d_in[2];
    const float* A_imag     = (const float*)d_in[3];
    float* out = (float*)d_out;
    s4d_kernel<<<HH, TPB, SM_TOTAL>>>(C, log_dt, log_A_real, A_imag, out);
}